// round 17
// baseline (speedup 1.0000x reference)
#include <cuda_runtime.h>

#define NB    4
#define NSEQ  2048
#define DIMV  512
#define NH    8
#define HD    64
#define NM    4
#define NROWS 16     // NB*NM
#define HM    32     // NH*NM
#define ASCALE 0.125f

// ---------------- scratch (device globals; no allocation allowed) ----------------
__device__ float g_qk[NB * HM * DIMV];
__device__ float g_dots[NB * HM * NSEQ];
__device__ float g_smax[NB * HM * 32];
__device__ float g_ssum[NB * HM * 32];
__device__ float g_ax[NB * HM * DIMV];

typedef unsigned long long u64;

__device__ __forceinline__ u64 fma2(u64 a, u64 b, u64 c) {
    u64 d; asm("fma.rn.f32x2 %0, %1, %2, %3;" : "=l"(d) : "l"(a), "l"(b), "l"(c)); return d;
}
__device__ __forceinline__ u64 pack2(float x, float y) {
    u64 r; asm("mov.b64 %0, {%1, %2};" : "=l"(r) : "f"(x), "f"(y)); return r;
}
__device__ __forceinline__ float2 unpack2(u64 v) {
    float2 f; asm("mov.b64 {%0, %1}, %2;" : "=f"(f.x), "=f"(f.y) : "l"(v)); return f;
}
__device__ __forceinline__ void redg4(float* p, float4 v) {
    asm volatile("red.global.add.v4.f32 [%0], {%1, %2, %3, %4};"
                 :: "l"(p), "f"(v.x), "f"(v.y), "f"(v.z), "f"(v.w) : "memory");
}
__device__ __forceinline__ void cpasync16(void* smem, const void* gmem) {
    unsigned saddr = (unsigned)__cvta_generic_to_shared(smem);
    asm volatile("cp.async.cg.shared.global [%0], [%1], 16;" :: "r"(saddr), "l"(gmem));
}
#define CP_COMMIT() asm volatile("cp.async.commit_group;")
#define CP_WAIT(n)  asm volatile("cp.async.wait_group %0;" :: "n"(n))

// ---------------- K12: q-slice (in-block) + qk + zero g_ax + init out = bo ----------------
// grid 128 = (h, kc). Each block computes q[:, h*64:(h+1)*64] itself from x and Wq
// (k-tiled through Ws, which is then reused for the Wkv tile), then the old k2 body.
__global__ void k12_qk(const float* __restrict__ x, const float* __restrict__ Wq,
                       const float* __restrict__ Wkv, const float* __restrict__ bo,
                       float* __restrict__ out) {
    __shared__ float XT[16][516];   // x rows (b*4+m) x 512   (33 KB)
    __shared__ float Ws[32][68];    // Wq k-tile, then Wkv kin-tile (8.7 KB)
    __shared__ float Qs[16][68];    // q slice [bm][64] (4.4 KB)  -> total ~46 KB
    int t = threadIdx.x;
    int h = blockIdx.x >> 4, kc = blockIdx.x & 15;
    int kin0 = kc << 5;
    // x rows (independent work first)
    for (int i = t; i < 2048; i += 256) {
        int r = i >> 7, kq = (i & 127) << 2;
        *(float4*)&XT[r][kq] =
            *(const float4*)&x[(size_t)(((r >> 2) * NSEQ) + (r & 3)) * DIMV + kq];
    }
    // zero g_ax + out = bo (REDG bases)
    int zi = blockIdx.x * 256 + t;
    g_ax[zi] = 0.f;
    g_ax[zi + 32768] = 0.f;
    if (zi < NROWS * DIMV) out[zi] = bo[zi & (DIMV - 1)];
    __syncthreads();
    // ---- phase 1: Qs = XT @ Wq[:, h*64:h*64+64], k-tiled by 32 ----
    int bm = t >> 4, c4 = (t & 15) << 2;
    float qa0 = 0.f, qa1 = 0.f, qa2 = 0.f, qa3 = 0.f;
    for (int kc2 = 0; kc2 < 16; kc2++) {
        {
            int r = t >> 4, c = (t & 15) << 2;
            *(float4*)&Ws[r][c] =
                *(const float4*)&Wq[(size_t)((kc2 << 5) + r) * DIMV + h * HD + c];
            *(float4*)&Ws[r + 16][c] =
                *(const float4*)&Wq[(size_t)((kc2 << 5) + r + 16) * DIMV + h * HD + c];
        }
        __syncthreads();
#pragma unroll
        for (int kk = 0; kk < 32; kk++) {
            float xv = XT[bm][(kc2 << 5) + kk];          // broadcast
            float4 w = *(const float4*)&Ws[kk][c4];      // conflict-free
            qa0 += xv * w.x; qa1 += xv * w.y; qa2 += xv * w.z; qa3 += xv * w.w;
        }
        __syncthreads();
    }
    *(float4*)&Qs[bm][c4] = make_float4(qa0, qa1, qa2, qa3);
    __syncthreads();
    // ---- phase 2: old k2 body — Ws <- Wkv kin-tile, qk = Qs @ Ws^T ----
#pragma unroll
    for (int i = 0; i < 2; i++) {
        int idx = t + (i << 8);
        int r = idx >> 4, c = (idx & 15) << 2;
        *(float4*)&Ws[r][c] =
            *(const float4*)&Wkv[(size_t)(kin0 + r) * (2 * DIMV) + h * HD + c];
    }
    __syncthreads();
    int kin = t & 15;
    float acc0 = 0.f, acc1 = 0.f;
#pragma unroll
    for (int dd = 0; dd < HD; dd += 4) {
        float4 q  = *(const float4*)&Qs[bm][dd];
        float4 w0 = *(const float4*)&Ws[kin][dd];
        float4 w1 = *(const float4*)&Ws[kin + 16][dd];
        acc0 += q.x * w0.x + q.y * w0.y + q.z * w0.z + q.w * w0.w;
        acc1 += q.x * w1.x + q.y * w1.y + q.z * w1.z + q.w * w1.w;
    }
    int b = bm >> 2, m = bm & 3;
    int hm = (h << 2) + m;
    g_qk[(b * HM + hm) * DIMV + kin0 + kin] = acc0;
    g_qk[(b * HM + hm) * DIMV + kin0 + kin + 16] = acc1;
}

// ---------------- K3: dots = qk @ x^T * SCALE + bias + chunk stats ----------------
// grid 128 = (b, n-chunk 64). 256 thr. X double-buffered + register-pipelined LDG.
__global__ void k3_dots(const float* __restrict__ x, const float* __restrict__ bias) {
    __shared__ float QKs[64][34];
    __shared__ float Xs[2][64][68];
    int t = threadIdx.x;
    int b = blockIdx.x >> 5, nb = blockIdx.x & 31;
    int n0 = nb << 6;
    int tn = t & 15, th = t >> 4;
    int n4 = tn << 2, hm2 = th << 1;
    int l_hm = t >> 3, l_q8 = t & 7;
    int l_nn = t >> 2, l_q4 = t & 3;
    float4 qv[2], xv[4];

    u64 acc[2][2];
#pragma unroll
    for (int j = 0; j < 2; j++) { acc[j][0] = pack2(0.f, 0.f); acc[j][1] = pack2(0.f, 0.f); }

#define K3_LDG(dt)                                                                        \
    {   int d0_ = (dt) << 6;                                                              \
        _Pragma("unroll")                                                                 \
        for (int i = 0; i < 2; i++)                                                       \
            qv[i] = *(const float4*)&g_qk[(b * HM + l_hm) * DIMV + d0_ + ((l_q8 + (i << 3)) << 2)]; \
        _Pragma("unroll")                                                                 \
        for (int i = 0; i < 4; i++)                                                       \
            xv[i] = *(const float4*)&x[(size_t)(b * NSEQ + n0 + l_nn) * DIMV + d0_ + ((l_q4 + (i << 2)) << 2)]; \
    }
#define K3_STS_QK()                                                                       \
    {   _Pragma("unroll")                                                                 \
        for (int i = 0; i < 2; i++) {                                                     \
            int kk = (l_q8 + (i << 3)) << 2;                                              \
            QKs[kk][l_hm] = qv[i].x; QKs[kk + 1][l_hm] = qv[i].y;                         \
            QKs[kk + 2][l_hm] = qv[i].z; QKs[kk + 3][l_hm] = qv[i].w;                     \
        }                                                                                 \
    }
#define K3_STS_X(buf)                                                                     \
    {   _Pragma("unroll")                                                                 \
        for (int i = 0; i < 4; i++) {                                                     \
            int kk = (l_q4 + (i << 2)) << 2;                                              \
            Xs[buf][kk][l_nn] = xv[i].x; Xs[buf][kk + 1][l_nn] = xv[i].y;                 \
            Xs[buf][kk + 2][l_nn] = xv[i].z; Xs[buf][kk + 3][l_nn] = xv[i].w;             \
        }                                                                                 \
    }

    K3_LDG(0); K3_STS_QK(); K3_STS_X(0);
    K3_LDG(1);
    __syncthreads();
    for (int dt = 0; dt < 8; dt++) {
        int buf = dt & 1;
#pragma unroll
        for (int kk = 0; kk < 64; kk++) {
            float2 a = *(const float2*)&QKs[kk][hm2];
            ulonglong2 xx = *(const ulonglong2*)&Xs[buf][kk][n4];
            u64 a0 = pack2(a.x, a.x), a1 = pack2(a.y, a.y);
            acc[0][0] = fma2(a0, xx.x, acc[0][0]);
            acc[0][1] = fma2(a0, xx.y, acc[0][1]);
            acc[1][0] = fma2(a1, xx.x, acc[1][0]);
            acc[1][1] = fma2(a1, xx.y, acc[1][1]);
        }
        __syncthreads();
        if (dt < 7) {
            K3_STS_QK();
            K3_STS_X(1 - buf);
            if (dt + 2 < 8) K3_LDG(dt + 2);
            __syncthreads();
        }
    }
#pragma unroll
    for (int j = 0; j < 2; j++) {
        int hm = hm2 + j;
        int h = hm >> 2, m = hm & 3;
        float4 bv = *(const float4*)&bias[(size_t)((b * NH + h) * NSEQ + m) * NSEQ + n0 + n4];
        float2 p0 = unpack2(acc[j][0]);
        float2 p1 = unpack2(acc[j][1]);
        float4 o = make_float4(p0.x * ASCALE + bv.x, p0.y * ASCALE + bv.y,
                               p1.x * ASCALE + bv.z, p1.y * ASCALE + bv.w);
        *(float4*)&g_dots[(b * HM + hm) * NSEQ + n0 + n4] = o;
        float M = fmaxf(fmaxf(o.x, o.y), fmaxf(o.z, o.w));
#pragma unroll
        for (int off = 8; off; off >>= 1) M = fmaxf(M, __shfl_xor_sync(0xffffffffu, M, off));
        float s = __expf(o.x - M) + __expf(o.y - M) + __expf(o.z - M) + __expf(o.w - M);
#pragma unroll
        for (int off = 8; off; off >>= 1) s += __shfl_xor_sync(0xffffffffu, s, off);
        if (tn == 0) {
            g_smax[(b * HM + hm) * 32 + nb] = M;
            g_ssum[(b * HM + hm) * 32 + nb] = s;
        }
    }
}

// ---------------- K5: ax += softmax(dots) @ x  (8hm x 8d per thread, cp.async, REDG) ----------------
// grid 128 = (b, n-chunk 64 idx 0..31). 256 thr = 8 warps: 4 hm-groups(8) x 2 d-halves(256).
__global__ void __launch_bounds__(256) k5_part(const float* __restrict__ x) {
    __shared__ float As[64][36];
    __shared__ __align__(16) float Xs[2][8][520];
    __shared__ float sM[32], sInv[32];
    int t = threadIdx.x;
    int b = blockIdx.x >> 5, nc = blockIdx.x & 31;
    int n0 = nc << 6;
    int td = t & 31, wid = t >> 5;
    int hm8 = (wid & 3) << 3;          // hm-group of 8
    int dbase = (wid >> 2) << 8;       // 0 or 256
    int c_nn = t >> 5, c_q = t & 31;

#define K5_ISSUE(s, buf)                                                                  \
    {   const float* gsrc = &x[(size_t)(b * NSEQ + n0 + ((s) << 3) + c_nn) * DIMV];       \
        _Pragma("unroll")                                                                 \
        for (int i = 0; i < 4; i++) {                                                     \
            int dd = (c_q + (i << 5)) << 2;                                               \
            cpasync16(&Xs[buf][c_nn][dd], gsrc + dd);                                     \
        }                                                                                 \
        CP_COMMIT();                                                                      \
    }

    K5_ISSUE(0, 0);
    K5_ISSUE(1, 1);
    // stats prologue: combine 32 chunk stats per row (overlaps async loads)
    {
        int row = t >> 3, j8 = t & 7;
        const float* pm = g_smax + (b * HM + row) * 32 + (j8 << 2);
        const float* ps = g_ssum + (b * HM + row) * 32 + (j8 << 2);
        float mv[4], sv[4];
        float M = -3.4e38f;
#pragma unroll
        for (int i = 0; i < 4; i++) { mv[i] = pm[i]; sv[i] = ps[i]; M = fmaxf(M, mv[i]); }
#pragma unroll
        for (int off = 4; off; off >>= 1) M = fmaxf(M, __shfl_xor_sync(0xffffffffu, M, off));
        float s = 0.f;
#pragma unroll
        for (int i = 0; i < 4; i++) s += __expf(mv[i] - M) * sv[i];
#pragma unroll
        for (int off = 4; off; off >>= 1) s += __shfl_xor_sync(0xffffffffu, s, off);
        if (j8 == 0) { sM[row] = M; sInv[row] = 1.f / s; }
    }
    __syncthreads();
    // As: 64n x 32hm transposed, exp applied (overlaps async loads)
    {
        int hm = t >> 3, q8 = t & 7;
        float M = sM[hm], is = sInv[hm];
#pragma unroll
        for (int i = 0; i < 2; i++) {
            int nn = (q8 + (i << 3)) << 2;
            float4 v = *(const float4*)&g_dots[(b * HM + hm) * NSEQ + n0 + nn];
            As[nn][hm]     = __expf(v.x - M) * is;
            As[nn + 1][hm] = __expf(v.y - M) * is;
            As[nn + 2][hm] = __expf(v.z - M) * is;
            As[nn + 3][hm] = __expf(v.w - M) * is;
        }
    }
    u64 acc[8][4];
#pragma unroll
    for (int j = 0; j < 8; j++)
#pragma unroll
        for (int k = 0; k < 4; k++) acc[j][k] = pack2(0.f, 0.f);

    for (int s = 0; s < 8; s++) {
        if (s < 7) { CP_WAIT(1); } else { CP_WAIT(0); }
        __syncthreads();
        int buf = s & 1;
#pragma unroll
        for (int nn2 = 0; nn2 < 8; nn2++) {
            int nn = (s << 3) + nn2;
            float4 aLo = *(const float4*)&As[nn][hm8];        // broadcast
            float4 aHi = *(const float4*)&As[nn][hm8 + 4];    // broadcast
            ulonglong2 x0 = *(const ulonglong2*)&Xs[buf][nn2][dbase + (td << 2)];
            ulonglong2 x1 = *(const ulonglong2*)&Xs[buf][nn2][dbase + 128 + (td << 2)];
            u64 a0 = pack2(aLo.x, aLo.x), a1 = pack2(aLo.y, aLo.y);
            u64 a2 = pack2(aLo.z, aLo.z), a3 = pack2(aLo.w, aLo.w);
            u64 a4 = pack2(aHi.x, aHi.x), a5 = pack2(aHi.y, aHi.y);
            u64 a6 = pack2(aHi.z, aHi.z), a7 = pack2(aHi.w, aHi.w);
            acc[0][0] = fma2(a0, x0.x, acc[0][0]); acc[0][1] = fma2(a0, x0.y, acc[0][1]);
            acc[0][2] = fma2(a0, x1.x, acc[0][2]); acc[0][3] = fma2(a0, x1.y, acc[0][3]);
            acc[1][0] = fma2(a1, x0.x, acc[1][0]); acc[1][1] = fma2(a1, x0.y, acc[1][1]);
            acc[1][2] = fma2(a1, x1.x, acc[1][2]); acc[1][3] = fma2(a1, x1.y, acc[1][3]);
            acc[2][0] = fma2(a2, x0.x, acc[2][0]); acc[2][1] = fma2(a2, x0.y, acc[2][1]);
            acc[2][2] = fma2(a2, x1.x, acc[2][2]); acc[2][3] = fma2(a2, x1.y, acc[2][3]);
            acc[3][0] = fma2(a3, x0.x, acc[3][0]); acc[3][1] = fma2(a3, x0.y, acc[3][1]);
            acc[3][2] = fma2(a3, x1.x, acc[3][2]); acc[3][3] = fma2(a3, x1.y, acc[3][3]);
            acc[4][0] = fma2(a4, x0.x, acc[4][0]); acc[4][1] = fma2(a4, x0.y, acc[4][1]);
            acc[4][2] = fma2(a4, x1.x, acc[4][2]); acc[4][3] = fma2(a4, x1.y, acc[4][3]);
            acc[5][0] = fma2(a5, x0.x, acc[5][0]); acc[5][1] = fma2(a5, x0.y, acc[5][1]);
            acc[5][2] = fma2(a5, x1.x, acc[5][2]); acc[5][3] = fma2(a5, x1.y, acc[5][3]);
            acc[6][0] = fma2(a6, x0.x, acc[6][0]); acc[6][1] = fma2(a6, x0.y, acc[6][1]);
            acc[6][2] = fma2(a6, x1.x, acc[6][2]); acc[6][3] = fma2(a6, x1.y, acc[6][3]);
            acc[7][0] = fma2(a7, x0.x, acc[7][0]); acc[7][1] = fma2(a7, x0.y, acc[7][1]);
            acc[7][2] = fma2(a7, x1.x, acc[7][2]); acc[7][3] = fma2(a7, x1.y, acc[7][3]);
        }
        __syncthreads();
        if (s + 2 < 8) { K5_ISSUE(s + 2, buf); }
    }
#pragma unroll
    for (int j = 0; j < 8; j++) {
        float* base = &g_ax[(size_t)(b * HM + hm8 + j) * DIMV + dbase];
        float2 p0 = unpack2(acc[j][0]), p1 = unpack2(acc[j][1]);
        redg4(base + (td << 2), make_float4(p0.x, p0.y, p1.x, p1.y));
        float2 p2 = unpack2(acc[j][2]), p3 = unpack2(acc[j][3]);
        redg4(base + 128 + (td << 2), make_float4(p2.x, p2.y, p3.x, p3.y));
    }
}

// ---------------- K78: out += (ax_h @ Wv[:, c0:c0+8]) @ Wo[c0:c0+8, :]  (fused) ----------------
// grid 64 (8 y-cols each). Phase 1 = old k7 into smem ys; phase 2 = rank-8 update REDG'd to out.
__global__ void k78(const float* __restrict__ Wkv, const float* __restrict__ Wo,
                    float* __restrict__ out) {
    __shared__ float A[NROWS * DIMV];
    __shared__ float ys[16][8];
    int t = threadIdx.x;
    int c0 = blockIdx.x * 8;
    int h = c0 >> 6;
    for (int i = t; i < NROWS * DIMV / 4; i += 256) {
        int r = i >> 7, k = (i & 127) << 2;
        *(float4*)&A[r * DIMV + k] =
            *(const float4*)&g_ax[(size_t)((((r >> 2) * NH + h) * NM) + (r & 3)) * DIMV + k];
    }
    __syncthreads();
    int cl = t & 7, kg = t >> 3;
    int c = c0 + cl;
    float acc[NROWS];
#pragma unroll
    for (int r = 0; r < NROWS; r++) acc[r] = 0.f;
    int k0 = kg << 4;
#pragma unroll
    for (int i = 0; i < 16; i++) {
        float w = Wkv[(size_t)(k0 + i) * (2 * DIMV) + DIMV + c];
#pragma unroll
        for (int r = 0; r < NROWS; r++) acc[r] += A[r * DIMV + k0 + i] * w;
    }
    __syncthreads();
#pragma unroll
    for (int r = 0; r < NROWS; r++) A[(kg << 7) + (r << 3) + cl] = acc[r];
    __syncthreads();
    if (t < 128) {
        int r = t >> 3, c2 = t & 7;
        float s = 0.f;
#pragma unroll
        for (int kg2 = 0; kg2 < 32; kg2++) s += A[(kg2 << 7) + (r << 3) + c2];
        ys[r][c2] = s;
    }
    __syncthreads();
    // phase 2: out[r, :] += ys[r, 0:8] @ Wo[c0:c0+8, :]
    {
        int r = t >> 4, oq = t & 15;
        float yv[8];
#pragma unroll
        for (int j = 0; j < 8; j++) yv[j] = ys[r][j];
#pragma unroll
        for (int i = 0; i < 8; i++) {
            int o = (oq + (i << 4)) << 2;
            float4 a = make_float4(0.f, 0.f, 0.f, 0.f);
#pragma unroll
            for (int j = 0; j < 8; j++) {
                float4 w = *(const float4*)&Wo[(size_t)(c0 + j) * DIMV + o];
                a.x += yv[j] * w.x; a.y += yv[j] * w.y;
                a.z += yv[j] * w.z; a.w += yv[j] * w.w;
            }
            redg4(&out[r * DIMV + o], a);
        }
    }
}

// ---------------- launch ----------------
extern "C" void kernel_launch(void* const* d_in, const int* in_sizes, int n_in,
                              void* d_out, int out_size) {
    const float* x    = (const float*)d_in[0];   // (4, 2048, 512)
    const float* bias = (const float*)d_in[1];   // (4, 8, 2048, 2048)
    const float* Wq   = (const float*)d_in[2];   // (512, 512)
    const float* Wkv  = (const float*)d_in[3];   // (512, 1024)
    const float* Wo   = (const float*)d_in[4];   // (512, 512)
    const float* bo   = (const float*)d_in[5];   // (512,)
    float* out = (float*)d_out;                  // (4, 4, 512)

    k12_qk<<<128, 256>>>(x, Wq, Wkv, bo, out);
    k3_dots<<<128, 256>>>(x, bias);
    k5_part<<<128, 256>>>(x);
    k78<<<64, 256>>>(Wkv, Wo, out);
}